// round 10
// baseline (speedup 1.0000x reference)
#include <cuda_runtime.h>
#include <cuda_fp16.h>
#include <cstdint>

// ============================================================================
// PatchMerged: Haar-DWT2 + LayerNorm + Linear fused into one fp16 GEMM over
// RAW x data (classic mma.sync m16n8k16 — harness targets base sm_103, no
// tcgen05). fp16 mantissa (10 bits + rn) == tf32 accuracy, 2x MACs/instr.
//
//   out[row, d] = rstd * (X @ Wf)[row, d] + (-rstd*mu) * S1[d] + S0[d]
//   mu  = 2 * (sum of 'a' samples) / 384          (Haar block is orthonormal)
//   var = (sum x^2 over all 384 raw samples)/384 - mu^2
//
// K ordering inside a 32-chunk: kloc = h*16 + cc*2 + w   (h,w = 2x2 position,
// cc = channel-in-chunk). This makes each GMEM float2 (w=0,w=1 pair) one
// fp16x2 word, and 4 channels = one 16B STS.128.
// ============================================================================

#define NOUT   192
#define KTOT   384
#define NCHUNK 12
#define NSTAGE 3
#define A_PITCH 80                      // 64B data + 16B pad: 20j mod 32 banks
#define A_STAGE (128 * A_PITCH)         // 10240 B
#define B_STAGE (192 * A_PITCH)         // 15360 B
#define SM_A0    0
#define SM_B0    (NSTAGE * A_STAGE)             // 30720
#define SM_RED   (SM_B0 + NSTAGE * B_STAGE)     // 76800 (float2 red[128][2])
#define SM_S1    (SM_RED + 2048)                // 78848
#define SM_S0    (SM_S1 + 768)                  // 79616
#define SM_RSTD  (SM_S0 + 768)                  // 80384
#define SM_ALPHA (SM_RSTD + 512)                // 80896
#define SM_TOTAL (SM_ALPHA + 512)               // 81408

// ---- precomputed weights (recomputed every launch; deterministic) ----
__device__ __align__(16) __half g_WfH[NOUT * KTOT];  // [d][kc*32 + kloc]
__device__ float g_S1[NOUT];
__device__ float g_S0[NOUT];

// ============================================================================
// helpers
// ============================================================================
__device__ __forceinline__ uint32_t s2u(const void* p) {
    uint32_t a;
    asm("{ .reg .u64 t; cvta.to.shared.u64 t, %1; cvt.u32.u64 %0, t; }"
        : "=r"(a) : "l"(p));
    return a;
}
__device__ __forceinline__ void cp_async16(uint32_t s, const void* g) {
    asm volatile("cp.async.ca.shared.global [%0], [%1], 16;" :: "r"(s), "l"(g));
}

#define LDSM4(r, a)                                                         \
    asm volatile(                                                           \
        "ldmatrix.sync.aligned.m8n8.x4.shared.b16 {%0,%1,%2,%3}, [%4];"     \
        : "=r"((r)[0]), "=r"((r)[1]), "=r"((r)[2]), "=r"((r)[3])            \
        : "r"(a))

#define MMA16816(d, a, b0r, b1r)                                            \
    asm volatile(                                                           \
        "mma.sync.aligned.m16n8k16.row.col.f32.f16.f16.f32 "                \
        "{%0,%1,%2,%3}, {%4,%5,%6,%7}, {%8,%9}, {%0,%1,%2,%3};"             \
        : "+f"((d)[0]), "+f"((d)[1]), "+f"((d)[2]), "+f"((d)[3])            \
        : "r"((a)[0]), "r"((a)[1]), "r"((a)[2]), "r"((a)[3]),               \
          "r"(b0r), "r"(b1r))

// ============================================================================
// Prep: fold Haar signs + norm_w into WfH (fp16, permuted kloc order); S1,S0.
//   sample (h,w) of channel c contributes to ll/lh/hl/hh with signs:
//   a(0,0): + + + +   b(0,1): + + - -   c(1,0): + - + -   d(1,1): + - - +
// ============================================================================
__global__ void prep_wfold(const float* __restrict__ nw, const float* __restrict__ w) {
    int c = blockIdx.x;    // 0..95
    int d = threadIdx.x;   // 0..191
    float w0 = nw[0 * 96 + c] * w[(0 * 96 + c) * NOUT + d];
    float w1 = nw[1 * 96 + c] * w[(1 * 96 + c) * NOUT + d];
    float w2 = nw[2 * 96 + c] * w[(2 * 96 + c) * NOUT + d];
    float w3 = nw[3 * 96 + c] * w[(3 * 96 + c) * NOUT + d];
    int base = d * KTOT + (c >> 3) * 32 + (c & 7) * 2;
    g_WfH[base + 0]  = __float2half_rn(0.5f * (w0 + w1 + w2 + w3));  // h0 w0
    g_WfH[base + 1]  = __float2half_rn(0.5f * (w0 + w1 - w2 - w3));  // h0 w1
    g_WfH[base + 16] = __float2half_rn(0.5f * (w0 - w1 + w2 - w3));  // h1 w0
    g_WfH[base + 17] = __float2half_rn(0.5f * (w0 - w1 - w2 + w3));  // h1 w1
}

__global__ void prep_s(const float* __restrict__ nw, const float* __restrict__ nb,
                       const float* __restrict__ w) {
    int d = threadIdx.x;
    float s1 = 0.f, s0 = 0.f;
    for (int j = 0; j < KTOT; j++) {
        float wv = w[j * NOUT + d];
        s1 += nw[j] * wv;
        s0 += nb[j] * wv;
    }
    g_S1[d] = s1;
    g_S0[d] = s0;
}

// ============================================================================
// Main kernel. CTA = (b, i): 128 rows x 192 cols. 8 warps: 2(M) x 4(N),
// warp tile 64x48 = 4x6 m16n8 tiles, 96 fp32 accums/thread. fp16 operands.
// ============================================================================
__global__ void __launch_bounds__(256)
pm_main(const float* __restrict__ x, float* __restrict__ out) {
    extern __shared__ char smem[];
    uint32_t sb = s2u(smem);
    int tid = threadIdx.x, lane = tid & 31, wid = tid >> 5;
    int wm = wid & 1, wn = wid >> 1;       // warp grid 2(M) x 4(N)
    int bx = blockIdx.x;
    int b = bx >> 7, i = bx & 127;

    float* S1s = (float*)(smem + SM_S1);
    float* S0s = (float*)(smem + SM_S0);
    if (tid < NOUT) { S1s[tid] = g_S1[tid]; S0s[tid] = g_S0[tid]; }

    // thread's fixed A-loader role: row j, half-grid h (warps 0-3: h=0)
    int j = tid & 127, h = tid >> 7;
    const float* xrow = x + (size_t)b * 96 * 65536 + (size_t)(2 * i + h) * 256 + 2 * j;

    // ldmatrix per-thread base offsets (add s*32 per k16-step)
    uint32_t offA[4], offB[3];
#pragma unroll
    for (int mt = 0; mt < 4; ++mt)
        offA[mt] = (uint32_t)((wm * 64 + mt * 16 + (lane & 7) + ((lane >> 3) & 1) * 8) * A_PITCH
                              + (lane >> 4) * 16);
#pragma unroll
    for (int np = 0; np < 3; ++np)
        offB[np] = (uint32_t)((wn * 48 + np * 16 + ((lane >> 4) << 3) + (lane & 7)) * A_PITCH
                              + ((lane >> 3) & 1) * 16);

    float acc[4][6][4];
#pragma unroll
    for (int mt = 0; mt < 4; ++mt)
#pragma unroll
        for (int nt = 0; nt < 6; ++nt)
#pragma unroll
            for (int e = 0; e < 4; ++e) acc[mt][nt][e] = 0.f;

    float suma = 0.f, ssq = 0.f;
    float2 areg[8];   // register prefetch: chunk's 16 samples (8 float2)

    auto ldgA = [&](int kc) {
#pragma unroll
        for (int un = 0; un < 2; ++un)     // channel block cb = un
#pragma unroll
            for (int u = 0; u < 4; ++u)    // channel within block
                areg[un * 4 + u] =
                    *(const float2*)(xrow + (size_t)(kc * 8 + un * 4 + u) * 65536);
    };
    auto stsA = [&](int kc) {
        uint32_t abase = sb + SM_A0 + (uint32_t)((kc % NSTAGE) * A_STAGE)
                       + (uint32_t)(j * A_PITCH + h * 32);
#pragma unroll
        for (int un = 0; un < 2; ++un) {
            uint32_t r[4];
#pragma unroll
            for (int u = 0; u < 4; ++u) {
                float2 v = areg[un * 4 + u];
                if (h == 0) suma += v.x;             // 'a' sample (h=0, w=0)
                ssq += v.x * v.x + v.y * v.y;
                __half2 hh = __floats2half2_rn(v.x, v.y);
                r[u] = *reinterpret_cast<uint32_t*>(&hh);
            }
            asm volatile("st.shared.v4.b32 [%0], {%1,%2,%3,%4};"
                         :: "r"(abase + (uint32_t)(un * 16)),
                            "r"(r[0]), "r"(r[1]), "r"(r[2]), "r"(r[3]));
        }
    };
    auto cpB = [&](int kc) {
        uint32_t bbase = sb + SM_B0 + (uint32_t)((kc % NSTAGE) * B_STAGE);
        const __half* g0 = g_WfH + kc * 32;
        int g = tid >> 6;                  // 16B granule 0..3
#pragma unroll
        for (int it = 0; it < 3; ++it) {
            int d = it * 64 + (tid & 63);
            cp_async16(bbase + (uint32_t)(d * A_PITCH + g * 16),
                       g0 + (size_t)d * KTOT + g * 8);
        }
    };

    // --- prologue: A0 staged, A1 in regs, B0/B1 in flight ---
    ldgA(0);
    cpB(0); asm volatile("cp.async.commit_group;" ::: "memory");
    cpB(1); asm volatile("cp.async.commit_group;" ::: "memory");
    stsA(0);
    ldgA(1);

    for (int n = 0; n < NCHUNK; ++n) {
        if (n < NCHUNK - 1)
            asm volatile("cp.async.wait_group 1;" ::: "memory");   // B(n) landed
        else
            asm volatile("cp.async.wait_group 0;" ::: "memory");
        __syncthreads();   // A(n) + B(n) visible; stages (n+1),(n+2) mod 3 free
        if (n + 2 < NCHUNK) {
            cpB(n + 2);
            asm volatile("cp.async.commit_group;" ::: "memory");
        }

        uint32_t abase = sb + SM_A0 + (uint32_t)((n % NSTAGE) * A_STAGE);
        uint32_t bbase = sb + SM_B0 + (uint32_t)((n % NSTAGE) * B_STAGE);
#pragma unroll
        for (int s = 0; s < 2; ++s) {      // two k16-steps per 32-chunk
            uint32_t bf[3][4], af[4][4];
#pragma unroll
            for (int np = 0; np < 3; ++np)
                LDSM4(bf[np], bbase + offB[np] + (uint32_t)(s * 32));
#pragma unroll
            for (int mt = 0; mt < 4; ++mt)
                LDSM4(af[mt], abase + offA[mt] + (uint32_t)(s * 32));
#pragma unroll
            for (int mt = 0; mt < 4; ++mt)
#pragma unroll
                for (int np = 0; np < 3; ++np) {
                    MMA16816(acc[mt][2 * np],     af[mt], bf[np][0], bf[np][1]);
                    MMA16816(acc[mt][2 * np + 1], af[mt], bf[np][2], bf[np][3]);
                }
        }

        if (n + 1 < NCHUNK) {
            stsA(n + 1);                  // convert + stage chunk n+1
            if (n + 2 < NCHUNK) ldgA(n + 2);   // prefetch chunk n+2 into regs
        }
    }

    // ---- LayerNorm stats reduction -> per-row rstd / alpha
    ((float2*)(smem + SM_RED))[j * 2 + h] = make_float2(suma, ssq);
    __syncthreads();
    if (tid < 128) {
        float2 p0 = ((float2*)(smem + SM_RED))[tid * 2 + 0];
        float2 p1 = ((float2*)(smem + SM_RED))[tid * 2 + 1];
        float sa = p0.x + p1.x;
        float sq = p0.y + p1.y;
        float mu = sa * (2.0f / 384.0f);
        float var = sq * (1.0f / 384.0f) - mu * mu;
        float rstd = rsqrtf(var + 1e-5f);
        ((float*)(smem + SM_RSTD))[tid] = rstd;
        ((float*)(smem + SM_ALPHA))[tid] = -rstd * mu;
    }
    __syncthreads();

    // ---- epilogue: affine + store (8B stores)
    int q = lane >> 2, p = lane & 3;
    const float* rstd_s = (const float*)(smem + SM_RSTD);
    const float* alpha_s = (const float*)(smem + SM_ALPHA);
    float* outb = out + (size_t)bx * 128 * NOUT;
#pragma unroll
    for (int mt = 0; mt < 4; ++mt) {
        int r0 = wm * 64 + mt * 16 + q;
        int r1 = r0 + 8;
        float rs0 = rstd_s[r0], al0 = alpha_s[r0];
        float rs1 = rstd_s[r1], al1 = alpha_s[r1];
#pragma unroll
        for (int nt = 0; nt < 6; ++nt) {
            int c0 = wn * 48 + nt * 8 + 2 * p;
            float s1a = S1s[c0], s1b = S1s[c0 + 1];
            float s0a = S0s[c0], s0b = S0s[c0 + 1];
            float2 v0, v1;
            v0.x = fmaf(rs0, acc[mt][nt][0], fmaf(al0, s1a, s0a));
            v0.y = fmaf(rs0, acc[mt][nt][1], fmaf(al0, s1b, s0b));
            v1.x = fmaf(rs1, acc[mt][nt][2], fmaf(al1, s1a, s0a));
            v1.y = fmaf(rs1, acc[mt][nt][3], fmaf(al1, s1b, s0b));
            *(float2*)(outb + (size_t)r0 * NOUT + c0) = v0;
            *(float2*)(outb + (size_t)r1 * NOUT + c0) = v1;
        }
    }
}

// ============================================================================
// Launch
// ============================================================================
extern "C" void kernel_launch(void* const* d_in, const int* in_sizes, int n_in,
                              void* d_out, int out_size) {
    const float* x  = (const float*)d_in[0];   // [16, 96, 256, 256]
    const float* nw = (const float*)d_in[1];   // [384]
    const float* nb = (const float*)d_in[2];   // [384]
    const float* w  = (const float*)d_in[3];   // [384, 192]
    float* out = (float*)d_out;                // [16, 16384, 192]
    (void)in_sizes; (void)n_in; (void)out_size;

    prep_wfold<<<96, 192>>>(nw, w);
    prep_s<<<1, 192>>>(nw, nb, w);

    cudaFuncSetAttribute(pm_main, cudaFuncAttributeMaxDynamicSharedMemorySize,
                         SM_TOTAL);
    pm_main<<<2048, 256, SM_TOTAL>>>(x, out);
}